// round 6
// baseline (speedup 1.0000x reference)
#include <cuda_runtime.h>
#include <cuda_bf16.h>

#define LQ   4096
#define NH   8
#define NB   2
#define DD   64
#define BH   (NB*NH)
#define UPAD 48
#define NC   128                // candidate buffer per bh (ncand <= 128)
#define CH   32
#define NCH  (LQ/CH)            // 128
#define KC   64                 // key chunk per inner iteration of fused kernel
#define NEG_INF -3.0e38f

// ---------------- scratch (static device globals; no allocation) ----------------
__device__ __nv_bfloat16 g_Kbf[NB*LQ*NH*DD];   // 8.4 MB bf16 copy of K
__device__ float g_M[BH*LQ];                   // approx M (stage 1)
__device__ int   g_cand[BH*NC];                // candidate query indices
__device__ float g_Mref[BH*NC];                // exact fp32 M of candidates
__device__ int   g_Mtop[BH*UPAD];
__device__ int   g_sel[BH*LQ];                 // -1 or u index
__device__ float g_update[BH*UPAD*DD];         // unnormalized: sum_k exp(s) * V
__device__ float g_rowsum[BH*UPAD];            // sum_k exp(s)
__device__ float g_csum[BH*NCH*DD];
__device__ float g_coff[BH*NCH*DD];

__device__ __forceinline__ int xoff(int b, int l, int h, int d) {
    return ((b*LQ + l)*NH + h)*DD + d;   // (B,L,H,D) layout of all I/O tensors
}

// ---- f32x2 packed-FMA helpers (ptxas will not auto-fuse; must be PTX) ----
__device__ __forceinline__ void ffma2(unsigned long long& d, unsigned long long a, unsigned long long b) {
    asm("fma.rn.f32x2 %0, %1, %2, %0;" : "+l"(d) : "l"(a), "l"(b));
}
__device__ __forceinline__ unsigned long long bcast2(float v) {
    unsigned r = __float_as_uint(v);
    unsigned long long d;
    asm("mov.b64 %0, {%1, %1};" : "=l"(d) : "r"(r));
    return d;
}
__device__ __forceinline__ float lo2(unsigned long long x){ return __uint_as_float((unsigned)(x & 0xffffffffu)); }
__device__ __forceinline__ float hi2(unsigned long long x){ return __uint_as_float((unsigned)(x >> 32)); }

// ---------------- Kernel 0: K -> bf16 copy (same layout) ----------------
__global__ __launch_bounds__(256) void k_cvtK(const float* __restrict__ K)
{
    int i = (blockIdx.x * 256 + threadIdx.x);           // one float4 per thread
    const float4 v = ((const float4*)K)[i];
    __nv_bfloat162 p0 = __floats2bfloat162_rn(v.x, v.y);
    __nv_bfloat162 p1 = __floats2bfloat162_rn(v.z, v.w);
    uint2 out;
    out.x = *(unsigned*)&p0;
    out.y = *(unsigned*)&p1;
    ((uint2*)g_Kbf)[i] = out;
}

// ---------------- Kernel A: approx M from bf16 K gather ----------------
// 1 warp/query; half-warp per sample (16 lanes x 8B = one 128B line per row); unroll x2.
__global__ __launch_bounds__(256) void k_sampleM_bf(
    const float* __restrict__ Q, const int* __restrict__ idxs, int U)
{
    int wid  = threadIdx.x >> 5;
    int lane = threadIdx.x & 31;
    int w    = blockIdx.x * 8 + wid;
    int bh   = w >> 12;
    int l    = w & (LQ - 1);
    int b = bh >> 3, h = bh & 7;
    int sp = lane >> 4;
    int lq = lane & 15;

    const float4* qrow = (const float4*)(Q + xoff(b, l, h, 0));
    float4 q4 = qrow[lq];
    const int* idxrow = idxs + l * U;

    float mxA = NEG_INF, smA = 0.0f;
    float mxB = NEG_INF, smB = 0.0f;
    int s = 0;
    for (; s + 4 <= U; s += 4) {
        int kiA = __ldg(&idxrow[s + sp]);
        int kiB = __ldg(&idxrow[s + 2 + sp]);
        uint2 ra = *(const uint2*)(g_Kbf + xoff(b, kiA, h, 4*lq));
        uint2 rb = *(const uint2*)(g_Kbf + xoff(b, kiB, h, 4*lq));
        float2 a0 = __bfloat1622float2(*(__nv_bfloat162*)&ra.x);
        float2 a1 = __bfloat1622float2(*(__nv_bfloat162*)&ra.y);
        float2 b0 = __bfloat1622float2(*(__nv_bfloat162*)&rb.x);
        float2 b1 = __bfloat1622float2(*(__nv_bfloat162*)&rb.y);
        float dA = q4.x*a0.x + q4.y*a0.y + q4.z*a1.x + q4.w*a1.y;
        float dB = q4.x*b0.x + q4.y*b0.y + q4.z*b1.x + q4.w*b1.y;
        #pragma unroll
        for (int o = 8; o >= 1; o >>= 1) {
            dA += __shfl_xor_sync(0xffffffffu, dA, o);
            dB += __shfl_xor_sync(0xffffffffu, dB, o);
        }
        mxA = fmaxf(mxA, dA); smA += dA;
        mxB = fmaxf(mxB, dB); smB += dB;
    }
    for (; s < U; s += 2) {
        int sEff  = s + sp;
        int valid = (sEff < U);
        int kidx  = valid ? __ldg(&idxrow[sEff]) : __ldg(&idxrow[0]);
        uint2 rr = *(const uint2*)(g_Kbf + xoff(b, kidx, h, 4*lq));
        float2 c0 = __bfloat1622float2(*(__nv_bfloat162*)&rr.x);
        float2 c1 = __bfloat1622float2(*(__nv_bfloat162*)&rr.y);
        float d = q4.x*c0.x + q4.y*c0.y + q4.z*c1.x + q4.w*c1.y;
        #pragma unroll
        for (int o = 8; o >= 1; o >>= 1)
            d += __shfl_xor_sync(0xffffffffu, d, o);
        if (valid) { mxA = fmaxf(mxA, d); smA += d; }
    }
    float mx = fmaxf(mxA, mxB);
    float sm = smA + smB;
    float mxo = __shfl_xor_sync(0xffffffffu, mx, 16);
    float smo = __shfl_xor_sync(0xffffffffu, sm, 16);
    mx = fmaxf(mx, mxo);
    sm += smo;
    if (lane == 0) g_M[bh*LQ + l] = mx - sm * (1.0f / (float)LQ);
}

// ---------------- Kernel B: radix-select top-ncand CANDIDATES per (b,h) (set only) ----------------
__global__ __launch_bounds__(256) void k_cand(int ncand)
{
    int bh  = blockIdx.x;
    int tid = threadIdx.x;
    __shared__ unsigned skeys[LQ];      // 16 KB
    __shared__ int hist[256];
    __shared__ int selcnt, s_rank;
    __shared__ unsigned s_prefix;

    for (int i = tid; i < LQ; i += 256) {
        unsigned ub = __float_as_uint(g_M[bh*LQ + i]);
        skeys[i] = (ub & 0x80000000u) ? ~ub : (ub | 0x80000000u);  // monotonic map
        g_sel[bh*LQ + i] = -1;
    }
    for (int i = tid; i < UPAD*DD; i += 256) g_update[bh*UPAD*DD + i] = 0.0f;
    if (tid < UPAD) g_rowsum[bh*UPAD + tid] = 0.0f;
    if (tid == 0) { selcnt = 0; s_prefix = 0; s_rank = ncand; }
    __syncthreads();

    unsigned mask = 0;
    for (int shift = 24; shift >= 0; shift -= 8) {
        hist[tid] = 0;
        __syncthreads();
        unsigned prefix = s_prefix;
        for (int i = tid; i < LQ; i += 256) {
            unsigned k = skeys[i];
            if ((k & mask) == prefix) atomicAdd(&hist[(k >> shift) & 255], 1);
        }
        __syncthreads();
        if (tid == 0) {
            int r = s_rank, acc = 0, d;
            for (d = 255; d >= 0; d--) {
                if (acc + hist[d] >= r) break;
                acc += hist[d];
            }
            s_rank   = r - acc;
            s_prefix = s_prefix | ((unsigned)d << shift);
        }
        __syncthreads();
        mask |= (0xFFu << shift);
    }

    unsigned T = s_prefix;
    for (int i = tid; i < LQ; i += 256) {
        unsigned k = skeys[i];
        if (k > T) {
            int u = atomicAdd(&selcnt, 1);
            g_cand[bh*NC + u] = i;
        }
    }
    __syncthreads();
    // fill remaining slots from the == group (any subset is fine: superset semantics)
    for (int i = tid; i < LQ; i += 256) {
        if (skeys[i] == T) {
            int u = atomicAdd(&selcnt, 1);
            if (u < ncand) g_cand[bh*NC + u] = i;
        }
    }
    __syncthreads();
    if (tid < NC && tid >= ncand) g_cand[bh*NC + tid] = 0;  // pad (unused)
    if (tid == 0 && selcnt < ncand) {                       // paranoia: pad with idx 0 dups never selected
        for (int u = selcnt; u < ncand; u++) g_cand[bh*NC + u] = 0;
    }
}

// ---------------- Kernel C: exact fp32 M for candidates ----------------
// 1 warp per (bh, cand); same half-warp fp32 gather as original kernel.
__global__ __launch_bounds__(256) void k_refine(
    const float* __restrict__ Q, const float* __restrict__ K,
    const int* __restrict__ idxs, int U, int ncand)
{
    int wid  = threadIdx.x >> 5;
    int lane = threadIdx.x & 31;
    int w    = blockIdx.x * 8 + wid;
    int bh   = w / ncand;
    int c    = w - bh * ncand;
    if (bh >= BH) return;
    int l = g_cand[bh*NC + c];
    int b = bh >> 3, h = bh & 7;
    int sp = lane >> 4;
    int lq = lane & 15;

    const float4* qrow = (const float4*)(Q + xoff(b, l, h, 0));
    float4 q4 = qrow[lq];
    const int* idxrow = idxs + l * U;

    float mx = NEG_INF, sm = 0.0f;
    for (int s = 0; s < U; s += 2) {
        int sEff  = s + sp;
        int valid = (sEff < U);
        int kidx  = valid ? __ldg(&idxrow[sEff]) : __ldg(&idxrow[0]);
        float4 k4 = *(const float4*)(K + xoff(b, kidx, h, 4*lq));
        float d = q4.x*k4.x + q4.y*k4.y + q4.z*k4.z + q4.w*k4.w;
        #pragma unroll
        for (int o = 8; o >= 1; o >>= 1)
            d += __shfl_xor_sync(0xffffffffu, d, o);
        if (valid) { mx = fmaxf(mx, d); sm += d; }
    }
    float mxo = __shfl_xor_sync(0xffffffffu, mx, 16);
    float smo = __shfl_xor_sync(0xffffffffu, sm, 16);
    mx = fmaxf(mx, mxo);
    sm += smo;
    if (lane == 0) g_Mref[bh*NC + c] = mx - sm * (1.0f / (float)LQ);
}

// ---------------- Kernel D: exact top-U among candidates (1 warp per bh) ----------------
__global__ __launch_bounds__(32) void k_sel45(int U, int ncand)
{
    int bh = blockIdx.x;
    int lane = threadIdx.x;
    float v[4]; int id[4];
    #pragma unroll
    for (int j = 0; j < 4; j++) {
        int c = j*32 + lane;
        if (c < ncand) { v[j] = g_Mref[bh*NC + c]; id[j] = g_cand[bh*NC + c]; }
        else           { v[j] = NEG_INF; id[j] = 0x7FFFFFFF; }
    }
    for (int u = 0; u < U; u++) {
        float lv = NEG_INF; int li = 0x7FFFFFFF, slot = -1;
        #pragma unroll
        for (int j = 0; j < 4; j++) {
            if (v[j] > lv || (v[j] == lv && id[j] < li)) { lv = v[j]; li = id[j]; slot = j; }
        }
        float bv = lv; int bi = li;
        #pragma unroll
        for (int o = 16; o >= 1; o >>= 1) {
            float ov = __shfl_xor_sync(0xffffffffu, bv, o);
            int   oi = __shfl_xor_sync(0xffffffffu, bi, o);
            if (ov > bv || (ov == bv && oi < bi)) { bv = ov; bi = oi; }
        }
        if (lv == bv && li == bi) {         // unique owner (indices distinct)
            v[slot] = NEG_INF;
            g_sel[bh*LQ + bi] = u;
        }
        if (lane == 0) g_Mtop[bh*UPAD + u] = bi;
    }
}

// ---------------- Kernel E: fused scores -> exp -> (exp@V) with f32x2 packed FMA ----------------
__global__ __launch_bounds__(256) void k_fused(
    const float* __restrict__ Q, const float* __restrict__ K,
    const float* __restrict__ V, int U)
{
    int bh = blockIdx.y;
    int b = bh >> 3, h = bh & 7;
    __shared__ float Qs[UPAD*66];   // [u][d] stride 66
    __shared__ float Ks[KC*66];     // [k][d] stride 66; reused as Ps[u][k]
    __shared__ float Vs[KC*66];     // [k][d] stride 66
    int tid = threadIdx.x;
    int tx = tid & 15, ty = tid >> 4;

    for (int i = tid; i < UPAD*DD; i += 256) {
        int u = i >> 6, d = i & 63;
        float v = 0.0f;
        if (u < U) { int l = g_Mtop[bh*UPAD + u]; v = Q[xoff(b, l, h, d)]; }
        Qs[u*66 + d] = v;
    }

    unsigned long long o2[3][2];
    #pragma unroll
    for (int j = 0; j < 3; j++) { o2[j][0] = 0ull; o2[j][1] = 0ull; }

    for (int c = 0; c < 2; c++) {
        int k0 = (blockIdx.x * 2 + c) * KC;
        __syncthreads();
        for (int i = tid; i < KC*DD; i += 256) {
            int k = i >> 6, d = i & 63;
            Ks[k*66 + d] = K[xoff(b, k0 + k, h, d)];
            Vs[k*66 + d] = V[xoff(b, k0 + k, h, d)];
        }
        __syncthreads();

        unsigned long long acc[3][4];
        #pragma unroll
        for (int j = 0; j < 3; j++)
            #pragma unroll
            for (int i = 0; i < 4; i++) acc[j][i] = 0ull;

        #pragma unroll 8
        for (int di = 0; di < 32; di++) {
            unsigned long long q2[3], k2[4];
            #pragma unroll
            for (int j = 0; j < 3; j++)
                q2[j] = *(const unsigned long long*)&Qs[(ty + 16*j)*66 + 2*di];
            #pragma unroll
            for (int i = 0; i < 4; i++)
                k2[i] = *(const unsigned long long*)&Ks[(tx + 16*i)*66 + 2*di];
            #pragma unroll
            for (int j = 0; j < 3; j++)
                #pragma unroll
                for (int i = 0; i < 4; i++) ffma2(acc[j][i], q2[j], k2[i]);
        }

        float ev[3][4];
        float rsum[3];
        #pragma unroll
        for (int j = 0; j < 3; j++) {
            rsum[j] = 0.0f;
            #pragma unroll
            for (int i = 0; i < 4; i++) {
                float sc = (lo2(acc[j][i]) + hi2(acc[j][i])) * 0.125f;  // 1/sqrt(64)
                float e = __expf(sc);
                ev[j][i] = e;
                rsum[j] += e;
            }
        }
        #pragma unroll
        for (int j = 0; j < 3; j++) {
            #pragma unroll
            for (int o = 8; o >= 1; o >>= 1)
                rsum[j] += __shfl_xor_sync(0xffffffffu, rsum[j], o);
        }
        if (tx == 0) {
            #pragma unroll
            for (int j = 0; j < 3; j++)
                atomicAdd(&g_rowsum[bh*UPAD + ty + 16*j], rsum[j]);
        }

        __syncthreads();
        float* Ps = Ks;
        #pragma unroll
        for (int j = 0; j < 3; j++)
            #pragma unroll
            for (int i = 0; i < 4; i++)
                Ps[(ty + 16*j)*66 + tx + 16*i] = ev[j][i];
        __syncthreads();

        #pragma unroll 8
        for (int k = 0; k < KC; k++) {
            unsigned long long p2[3], v2[2];
            #pragma unroll
            for (int j = 0; j < 3; j++) p2[j] = bcast2(Ps[(ty + 16*j)*66 + k]);
            #pragma unroll
            for (int i = 0; i < 2; i++)
                v2[i] = *(const unsigned long long*)&Vs[k*66 + 2*(tx + 16*i)];
            #pragma unroll
            for (int j = 0; j < 3; j++)
                #pragma unroll
                for (int i = 0; i < 2; i++) ffma2(o2[j][i], p2[j], v2[i]);
        }
    }

    #pragma unroll
    for (int j = 0; j < 3; j++) {
        int u = ty + 16*j;
        #pragma unroll
        for (int i = 0; i < 2; i++) {
            int d = 2*(tx + 16*i);
            atomicAdd(&g_update[(bh*UPAD + u)*DD + d],     lo2(o2[j][i]));
            atomicAdd(&g_update[(bh*UPAD + u)*DD + d + 1], hi2(o2[j][i]));
        }
    }
}

// ---------------- Kernel F1: per-chunk V sums ----------------
__global__ __launch_bounds__(64) void k_csum1(const float* __restrict__ V)
{
    int ch = blockIdx.x, bh = blockIdx.y, d = threadIdx.x;
    int b = bh >> 3, h = bh & 7;
    float acc = 0.0f;
    int base = xoff(b, ch*CH, h, d);
    #pragma unroll
    for (int i = 0; i < CH; i++) acc += V[base + i*(NH*DD)];
    g_csum[(bh*NCH + ch)*DD + d] = acc;
}

// ---------------- Kernel F2: exclusive scan of chunk sums ----------------
__global__ __launch_bounds__(1024) void k_csum2()
{
    int t = threadIdx.x;           // 1024 = BH*DD
    int bh = t >> 6, d = t & 63;
    float run = 0.0f;
    #pragma unroll 8
    for (int ch = 0; ch < NCH; ch++) {
        int ix = (bh*NCH + ch)*DD + d;
        float v = g_csum[ix];
        g_coff[ix] = run;
        run += v;
    }
}

// ---------------- Kernel F3: final cumsum + scatter of normalized update + output ----------------
__global__ __launch_bounds__(64) void k_final(const float* __restrict__ V, float* __restrict__ out)
{
    int ch = blockIdx.x, bh = blockIdx.y, d = threadIdx.x;
    int b = bh >> 3, h = bh & 7;
    float acc = g_coff[(bh*NCH + ch)*DD + d];
    int l0 = ch*CH;
    #pragma unroll 4
    for (int i = 0; i < CH; i++) {
        int l = l0 + i;
        int o = xoff(b, l, h, d);
        acc += V[o];
        int s = __ldg(&g_sel[bh*LQ + l]);
        if (s >= 0) {
            float inv = 1.0f / __ldg(&g_rowsum[bh*UPAD + s]);
            out[o] = g_update[(bh*UPAD + s)*DD + d] * inv;
        } else {
            out[o] = acc;
        }
    }
}

// ---------------- launch ----------------
// Order: ncu captures launch 4 -> k_sampleM_bf (the new stage-1 gather).
extern "C" void kernel_launch(void* const* d_in, const int* in_sizes, int n_in,
                              void* d_out, int out_size)
{
    const float* Q   = (const float*)d_in[0];
    const float* K   = (const float*)d_in[1];
    const float* V   = (const float*)d_in[2];
    const int*   idx = (const int*)  d_in[3];
    float* out = (float*)d_out;
    int U = in_sizes[3] / LQ;     // 45
    int ncand = (2*U + 6 <= NC) ? 2*U + 6 : NC;   // 96 for U=45

    k_cvtK     <<<NB*LQ*NH*DD/4/256, 256>>>(K);              // 1
    k_csum1    <<<dim3(NCH, BH), 64>>>(V);                   // 2
    k_csum2    <<<1, 1024>>>();                              // 3
    k_sampleM_bf<<<BH*LQ/8, 256>>>(Q, idx, U);               // 4  <- profiled
    k_cand     <<<BH, 256>>>(ncand);                         // 5
    k_refine   <<<(BH*ncand + 7)/8, 256>>>(Q, K, idx, U, ncand); // 6
    k_sel45    <<<BH, 32>>>(U, ncand);                       // 7
    k_fused    <<<dim3(LQ/(2*KC), BH), 256>>>(Q, K, V, U);   // 8
    k_final    <<<dim3(NCH, BH), 64>>>(V, out);              // 9
}

// round 7
// speedup vs baseline: 1.0937x; 1.0937x over previous
#include <cuda_runtime.h>
#include <cuda_bf16.h>

#define LQ   4096
#define NH   8
#define NB   2
#define DD   64
#define BH   (NB*NH)
#define UPAD 48
#define NC   128                // candidate buffer per bh (ncand <= 128)
#define CH   32
#define NCH  (LQ/CH)            // 128
#define KC   64                 // key chunk per inner iteration of fused kernel
#define NEG_INF -3.0e38f

// ---------------- scratch (static device globals; no allocation) ----------------
__device__ __align__(16) __nv_bfloat16 g_Kbf[NB*LQ*NH*DD];   // 8.4 MB bf16 copy of K
__device__ float g_M[BH*LQ];                   // approx M (stage 1)
__device__ int   g_cand[BH*NC];                // candidate query indices
__device__ float g_Mref[BH*NC];                // exact fp32 M of candidates
__device__ int   g_Mtop[BH*UPAD];
__device__ int   g_sel[BH*LQ];                 // -1 or u index
__device__ float g_update[BH*UPAD*DD];         // unnormalized: sum_k exp(s) * V
__device__ float g_rowsum[BH*UPAD];            // sum_k exp(s)
__device__ float g_csum[BH*NCH*DD];
__device__ float g_coff[BH*NCH*DD];

__device__ __forceinline__ int xoff(int b, int l, int h, int d) {
    return ((b*LQ + l)*NH + h)*DD + d;   // (B,L,H,D) layout of all I/O tensors
}

// ---- f32x2 packed-FMA helpers (ptxas will not auto-fuse; must be PTX) ----
__device__ __forceinline__ void ffma2(unsigned long long& d, unsigned long long a, unsigned long long b) {
    asm("fma.rn.f32x2 %0, %1, %2, %0;" : "+l"(d) : "l"(a), "l"(b));
}
__device__ __forceinline__ unsigned long long bcast2(float v) {
    unsigned r = __float_as_uint(v);
    unsigned long long d;
    asm("mov.b64 %0, {%1, %1};" : "=l"(d) : "r"(r));
    return d;
}
__device__ __forceinline__ float lo2(unsigned long long x){ return __uint_as_float((unsigned)(x & 0xffffffffu)); }
__device__ __forceinline__ float hi2(unsigned long long x){ return __uint_as_float((unsigned)(x >> 32)); }

// 8-wide bf16 dot against fp32 q (elems 8*t8 .. 8*t8+7)
__device__ __forceinline__ float dot8(float4 qa, float4 qb, uint4 r) {
    float2 p0 = __bfloat1622float2(*(__nv_bfloat162*)&r.x);
    float2 p1 = __bfloat1622float2(*(__nv_bfloat162*)&r.y);
    float2 p2 = __bfloat1622float2(*(__nv_bfloat162*)&r.z);
    float2 p3 = __bfloat1622float2(*(__nv_bfloat162*)&r.w);
    return qa.x*p0.x + qa.y*p0.y + qa.z*p1.x + qa.w*p1.y
         + qb.x*p2.x + qb.y*p2.y + qb.z*p3.x + qb.w*p3.y;
}

// ---------------- Kernel 0: K -> bf16 copy (same layout), half-grid per call ----------------
__global__ __launch_bounds__(256) void k_cvtK(const float* __restrict__ K, int off)
{
    int i = blockIdx.x * 256 + threadIdx.x + off;        // one float4 per thread
    const float4 v = ((const float4*)K)[i];
    __nv_bfloat162 p0 = __floats2bfloat162_rn(v.x, v.y);
    __nv_bfloat162 p1 = __floats2bfloat162_rn(v.z, v.w);
    uint2 out;
    out.x = *(unsigned*)&p0;
    out.y = *(unsigned*)&p1;
    ((uint2*)g_Kbf)[i] = out;
}

// ---------------- Kernel A: approx M from bf16 K gather ----------------
// 1 warp/query; 8-lane group per sample (LDG.128 = full 128B row), 2 chains -> 8 samples/iter.
__global__ __launch_bounds__(256) void k_sampleM_bf(
    const float* __restrict__ Q, const int* __restrict__ idxs, int U)
{
    int wid  = threadIdx.x >> 5;
    int lane = threadIdx.x & 31;
    int w    = blockIdx.x * 8 + wid;
    int bh   = w >> 12;
    int l    = w & (LQ - 1);
    int b = bh >> 3, h = bh & 7;
    int g  = lane >> 3;          // group 0..3
    int t8 = lane & 7;           // 16B slot within the 128B row

    const float4* qrow = (const float4*)(Q + xoff(b, l, h, 0));
    float4 qa = qrow[2*t8];
    float4 qb = qrow[2*t8 + 1];
    const int* idxrow = idxs + l * U;
    const __nv_bfloat16* Kb = g_Kbf + ((b*LQ)*NH + h)*DD;   // + kidx*(NH*DD)

    float mxA = NEG_INF, smA = 0.0f;
    float mxB = NEG_INF, smB = 0.0f;
    int s = 0;
    for (; s + 8 <= U; s += 8) {
        int kiA = __ldg(&idxrow[s + g]);
        int kiB = __ldg(&idxrow[s + 4 + g]);
        uint4 ra = *(const uint4*)(Kb + kiA*(NH*DD) + 8*t8);
        uint4 rb = *(const uint4*)(Kb + kiB*(NH*DD) + 8*t8);
        float dA = dot8(qa, qb, ra);
        float dB = dot8(qa, qb, rb);
        #pragma unroll
        for (int o = 4; o >= 1; o >>= 1) {
            dA += __shfl_xor_sync(0xffffffffu, dA, o);
            dB += __shfl_xor_sync(0xffffffffu, dB, o);
        }
        mxA = fmaxf(mxA, dA); smA += dA;
        mxB = fmaxf(mxB, dB); smB += dB;
    }
    for (; s < U; s += 4) {
        int sE = s + g;
        int valid = (sE < U);
        int ki = valid ? __ldg(&idxrow[sE]) : __ldg(&idxrow[0]);
        uint4 r = *(const uint4*)(Kb + ki*(NH*DD) + 8*t8);
        float d = dot8(qa, qb, r);
        #pragma unroll
        for (int o = 4; o >= 1; o >>= 1)
            d += __shfl_xor_sync(0xffffffffu, d, o);
        if (valid) { mxA = fmaxf(mxA, d); smA += d; }
    }
    float mx = fmaxf(mxA, mxB);
    float sm = smA + smB;
    // reduce across the 4 groups
    mx = fmaxf(mx, __shfl_xor_sync(0xffffffffu, mx, 8));
    sm +=          __shfl_xor_sync(0xffffffffu, sm, 8);
    mx = fmaxf(mx, __shfl_xor_sync(0xffffffffu, mx, 16));
    sm +=          __shfl_xor_sync(0xffffffffu, sm, 16);
    if (lane == 0) g_M[bh*LQ + l] = mx - sm * (1.0f / (float)LQ);
}

// ---------------- Kernel B: radix-select top-ncand CANDIDATES per (b,h) + csum2 scan ----------------
__global__ __launch_bounds__(256) void k_cand(int ncand)
{
    int bh  = blockIdx.x;
    int tid = threadIdx.x;
    __shared__ unsigned skeys[LQ];      // 16 KB
    __shared__ int hist[256];
    __shared__ int selcnt, s_rank;
    __shared__ unsigned s_prefix;

    for (int i = tid; i < LQ; i += 256) {
        unsigned ub = __float_as_uint(g_M[bh*LQ + i]);
        skeys[i] = (ub & 0x80000000u) ? ~ub : (ub | 0x80000000u);  // monotonic map
        g_sel[bh*LQ + i] = -1;
    }
    for (int i = tid; i < UPAD*DD; i += 256) g_update[bh*UPAD*DD + i] = 0.0f;
    if (tid < UPAD) g_rowsum[bh*UPAD + tid] = 0.0f;
    if (tid == 0) { selcnt = 0; s_prefix = 0; s_rank = ncand; }
    __syncthreads();

    // merged csum2: threads 64..127 do this bh's exclusive chunk scan while
    // the radix passes run (they rejoin at the next __syncthreads anyway)
    if (tid >= 64 && tid < 128) {
        int d = tid - 64;
        float run = 0.0f;
        #pragma unroll 8
        for (int ch = 0; ch < NCH; ch++) {
            int ix = (bh*NCH + ch)*DD + d;
            float v = g_csum[ix];
            g_coff[ix] = run;
            run += v;
        }
    }

    unsigned mask = 0;
    for (int shift = 24; shift >= 0; shift -= 8) {
        hist[tid] = 0;
        __syncthreads();
        unsigned prefix = s_prefix;
        for (int i = tid; i < LQ; i += 256) {
            unsigned k = skeys[i];
            if ((k & mask) == prefix) atomicAdd(&hist[(k >> shift) & 255], 1);
        }
        __syncthreads();
        if (tid == 0) {
            int r = s_rank, acc = 0, d;
            for (d = 255; d >= 0; d--) {
                if (acc + hist[d] >= r) break;
                acc += hist[d];
            }
            s_rank   = r - acc;
            s_prefix = s_prefix | ((unsigned)d << shift);
        }
        __syncthreads();
        mask |= (0xFFu << shift);
    }

    unsigned T = s_prefix;
    for (int i = tid; i < LQ; i += 256) {
        unsigned k = skeys[i];
        if (k > T) {
            int u = atomicAdd(&selcnt, 1);
            g_cand[bh*NC + u] = i;
        }
    }
    __syncthreads();
    for (int i = tid; i < LQ; i += 256) {   // fill from == group (superset semantics)
        if (skeys[i] == T) {
            int u = atomicAdd(&selcnt, 1);
            if (u < ncand) g_cand[bh*NC + u] = i;
        }
    }
    __syncthreads();
    if (tid == 0 && selcnt < ncand) {
        for (int u = selcnt; u < ncand; u++) g_cand[bh*NC + u] = 0;
    }
}

// ---------------- Kernel C: exact fp32 M for candidates (unrolled x2 gather) ----------------
__global__ __launch_bounds__(256) void k_refine(
    const float* __restrict__ Q, const float* __restrict__ K,
    const int* __restrict__ idxs, int U, int ncand)
{
    int wid  = threadIdx.x >> 5;
    int lane = threadIdx.x & 31;
    int w    = blockIdx.x * 8 + wid;
    int bh   = w / ncand;
    int c    = w - bh * ncand;
    if (bh >= BH) return;
    int l = g_cand[bh*NC + c];
    int b = bh >> 3, h = bh & 7;
    int sp = lane >> 4;
    int lq = lane & 15;

    const float4* qrow = (const float4*)(Q + xoff(b, l, h, 0));
    float4 q4 = qrow[lq];
    const int* idxrow = idxs + l * U;

    float mxA = NEG_INF, smA = 0.0f;
    float mxB = NEG_INF, smB = 0.0f;
    int s = 0;
    for (; s + 4 <= U; s += 4) {
        int kiA = __ldg(&idxrow[s + sp]);
        int kiB = __ldg(&idxrow[s + 2 + sp]);
        float4 kA = *(const float4*)(K + xoff(b, kiA, h, 4*lq));
        float4 kB = *(const float4*)(K + xoff(b, kiB, h, 4*lq));
        float dA = q4.x*kA.x + q4.y*kA.y + q4.z*kA.z + q4.w*kA.w;
        float dB = q4.x*kB.x + q4.y*kB.y + q4.z*kB.z + q4.w*kB.w;
        #pragma unroll
        for (int o = 8; o >= 1; o >>= 1) {
            dA += __shfl_xor_sync(0xffffffffu, dA, o);
            dB += __shfl_xor_sync(0xffffffffu, dB, o);
        }
        mxA = fmaxf(mxA, dA); smA += dA;
        mxB = fmaxf(mxB, dB); smB += dB;
    }
    for (; s < U; s += 2) {
        int sEff  = s + sp;
        int valid = (sEff < U);
        int kidx  = valid ? __ldg(&idxrow[sEff]) : __ldg(&idxrow[0]);
        float4 k4 = *(const float4*)(K + xoff(b, kidx, h, 4*lq));
        float d = q4.x*k4.x + q4.y*k4.y + q4.z*k4.z + q4.w*k4.w;
        #pragma unroll
        for (int o = 8; o >= 1; o >>= 1)
            d += __shfl_xor_sync(0xffffffffu, d, o);
        if (valid) { mxA = fmaxf(mxA, d); smA += d; }
    }
    float mx = fmaxf(mxA, mxB);
    float sm = smA + smB;
    float mxo = __shfl_xor_sync(0xffffffffu, mx, 16);
    float smo = __shfl_xor_sync(0xffffffffu, sm, 16);
    mx = fmaxf(mx, mxo);
    sm += smo;
    if (lane == 0) g_Mref[bh*NC + c] = mx - sm * (1.0f / (float)LQ);
}

// ---------------- Kernel D: exact top-U among candidates (1 warp per bh) ----------------
__global__ __launch_bounds__(32) void k_sel45(int U, int ncand)
{
    int bh = blockIdx.x;
    int lane = threadIdx.x;
    float v[4]; int id[4];
    #pragma unroll
    for (int j = 0; j < 4; j++) {
        int c = j*32 + lane;
        if (c < ncand) { v[j] = g_Mref[bh*NC + c]; id[j] = g_cand[bh*NC + c]; }
        else           { v[j] = NEG_INF; id[j] = 0x7FFFFFFF; }
    }
    for (int u = 0; u < U; u++) {
        float lv = NEG_INF; int li = 0x7FFFFFFF, slot = -1;
        #pragma unroll
        for (int j = 0; j < 4; j++) {
            if (v[j] > lv || (v[j] == lv && id[j] < li)) { lv = v[j]; li = id[j]; slot = j; }
        }
        float bv = lv; int bi = li;
        #pragma unroll
        for (int o = 16; o >= 1; o >>= 1) {
            float ov = __shfl_xor_sync(0xffffffffu, bv, o);
            int   oi = __shfl_xor_sync(0xffffffffu, bi, o);
            if (ov > bv || (ov == bv && oi < bi)) { bv = ov; bi = oi; }
        }
        if (lv == bv && li == bi) {         // unique owner (indices distinct)
            v[slot] = NEG_INF;
            g_sel[bh*LQ + bi] = u;
        }
        if (lane == 0) g_Mtop[bh*UPAD + u] = bi;
    }
}

// ---------------- Kernel E: fused scores -> exp -> (exp@V) with f32x2 packed FMA ----------------
__global__ __launch_bounds__(256) void k_fused(
    const float* __restrict__ Q, const float* __restrict__ K,
    const float* __restrict__ V, int U)
{
    int bh = blockIdx.y;
    int b = bh >> 3, h = bh & 7;
    __shared__ float Qs[UPAD*66];   // [u][d] stride 66
    __shared__ float Ks[KC*66];     // [k][d] stride 66; reused as Ps[u][k]
    __shared__ float Vs[KC*66];     // [k][d] stride 66
    int tid = threadIdx.x;
    int tx = tid & 15, ty = tid >> 4;

    for (int i = tid; i < UPAD*DD; i += 256) {
        int u = i >> 6, d = i & 63;
        float v = 0.0f;
        if (u < U) { int l = g_Mtop[bh*UPAD + u]; v = Q[xoff(b, l, h, d)]; }
        Qs[u*66 + d] = v;
    }

    unsigned long long o2[3][2];
    #pragma unroll
    for (int j = 0; j < 3; j++) { o2[j][0] = 0ull; o2[j][1] = 0ull; }

    for (int c = 0; c < 2; c++) {
        int k0 = (blockIdx.x * 2 + c) * KC;
        __syncthreads();
        for (int i = tid; i < KC*DD; i += 256) {
            int k = i >> 6, d = i & 63;
            Ks[k*66 + d] = K[xoff(b, k0 + k, h, d)];
            Vs[k*66 + d] = V[xoff(b, k0 + k, h, d)];
        }
        __syncthreads();

        unsigned long long acc[3][4];
        #pragma unroll
        for (int j = 0; j < 3; j++)
            #pragma unroll
            for (int i = 0; i < 4; i++) acc[j][i] = 0ull;

        #pragma unroll 8
        for (int di = 0; di < 32; di++) {
            unsigned long long q2[3], k2[4];
            #pragma unroll
            for (int j = 0; j < 3; j++)
                q2[j] = *(const unsigned long long*)&Qs[(ty + 16*j)*66 + 2*di];
            #pragma unroll
            for (int i = 0; i < 4; i++)
                k2[i] = *(const unsigned long long*)&Ks[(tx + 16*i)*66 + 2*di];
            #pragma unroll
            for (int j = 0; j < 3; j++)
                #pragma unroll
                for (int i = 0; i < 4; i++) ffma2(acc[j][i], q2[j], k2[i]);
        }

        float ev[3][4];
        float rsum[3];
        #pragma unroll
        for (int j = 0; j < 3; j++) {
            rsum[j] = 0.0f;
            #pragma unroll
            for (int i = 0; i < 4; i++) {
                float sc = (lo2(acc[j][i]) + hi2(acc[j][i])) * 0.125f;  // 1/sqrt(64)
                float e = __expf(sc);
                ev[j][i] = e;
                rsum[j] += e;
            }
        }
        #pragma unroll
        for (int j = 0; j < 3; j++) {
            #pragma unroll
            for (int o = 8; o >= 1; o >>= 1)
                rsum[j] += __shfl_xor_sync(0xffffffffu, rsum[j], o);
        }
        if (tx == 0) {
            #pragma unroll
            for (int j = 0; j < 3; j++)
                atomicAdd(&g_rowsum[bh*UPAD + ty + 16*j], rsum[j]);
        }

        __syncthreads();
        float* Ps = Ks;
        #pragma unroll
        for (int j = 0; j < 3; j++)
            #pragma unroll
            for (int i = 0; i < 4; i++)
                Ps[(ty + 16*j)*66 + tx + 16*i] = ev[j][i];
        __syncthreads();

        #pragma unroll 8
        for (int k = 0; k < KC; k++) {
            unsigned long long p2[3], v2[2];
            #pragma unroll
            for (int j = 0; j < 3; j++) p2[j] = bcast2(Ps[(ty + 16*j)*66 + k]);
            #pragma unroll
            for (int i = 0; i < 2; i++)
                v2[i] = *(const unsigned long long*)&Vs[k*66 + 2*(tx + 16*i)];
            #pragma unroll
            for (int j = 0; j < 3; j++)
                #pragma unroll
                for (int i = 0; i < 2; i++) ffma2(o2[j][i], p2[j], v2[i]);
        }
    }

    #pragma unroll
    for (int j = 0; j < 3; j++) {
        int u = ty + 16*j;
        #pragma unroll
        for (int i = 0; i < 2; i++) {
            int d = 2*(tx + 16*i);
            atomicAdd(&g_update[(bh*UPAD + u)*DD + d],     lo2(o2[j][i]));
            atomicAdd(&g_update[(bh*UPAD + u)*DD + d + 1], hi2(o2[j][i]));
        }
    }
}

// ---------------- Kernel F1: per-chunk V sums (256 thr, 4-way k-split, depth 8) ----------------
__global__ __launch_bounds__(256) void k_csum1(const float* __restrict__ V)
{
    int ch = blockIdx.x, bh = blockIdx.y;
    int b = bh >> 3, h = bh & 7;
    int d = threadIdx.x & 63, seg = threadIdx.x >> 6;
    __shared__ float part[4][DD];
    float acc = 0.0f;
    int base = xoff(b, ch*CH + seg*8, h, d);
    #pragma unroll
    for (int i = 0; i < 8; i++) acc += V[base + i*(NH*DD)];
    part[seg][d] = acc;
    __syncthreads();
    if (threadIdx.x < 64)
        g_csum[(bh*NCH + ch)*DD + d] = part[0][d] + part[1][d] + part[2][d] + part[3][d];
}

// ---------------- Kernel F3: final cumsum + scatter of normalized update + output ----------------
__global__ __launch_bounds__(64) void k_final(const float* __restrict__ V, float* __restrict__ out)
{
    int ch = blockIdx.x, bh = blockIdx.y, d = threadIdx.x;
    int b = bh >> 3, h = bh & 7;
    float acc = g_coff[(bh*NCH + ch)*DD + d];
    int l0 = ch*CH;
    #pragma unroll 8
    for (int i = 0; i < CH; i++) {
        int l = l0 + i;
        int o = xoff(b, l, h, d);
        acc += V[o];
        int s = __ldg(&g_sel[bh*LQ + l]);
        if (s >= 0) {
            float inv = 1.0f / __ldg(&g_rowsum[bh*UPAD + s]);
            out[o] = g_update[(bh*UPAD + s)*DD + d] * inv;
        } else {
            out[o] = acc;
        }
    }
}

// ---------------- launch ----------------
// Order: ncu captures launch 4 -> k_sampleM_bf (the redesigned gather).
extern "C" void kernel_launch(void* const* d_in, const int* in_sizes, int n_in,
                              void* d_out, int out_size)
{
    const float* Q   = (const float*)d_in[0];
    const float* K   = (const float*)d_in[1];
    const float* V   = (const float*)d_in[2];
    const int*   idx = (const int*)  d_in[3];
    float* out = (float*)d_out;
    int U = in_sizes[3] / LQ;     // 45
    int ncand = (2*U + 6 <= NC) ? 2*U + 6 : NC;   // 96 for U=45
    const int NF4 = NB*LQ*NH*DD/4;                 // total float4 elems in K

    k_csum1    <<<dim3(NCH, BH), 256>>>(V);                  // 1
    k_cvtK     <<<NF4/2/256, 256>>>(K, 0);                   // 2
    k_cvtK     <<<NF4/2/256, 256>>>(K, NF4/2);               // 3
    k_sampleM_bf<<<BH*LQ/8, 256>>>(Q, idx, U);               // 4  <- profiled
    k_cand     <<<BH, 256>>>(ncand);                         // 5  (+ csum2 scan)
    k_refine   <<<(BH*ncand + 7)/8, 256>>>(Q, K, idx, U, ncand); // 6
    k_sel45    <<<BH, 32>>>(U, ncand);                       // 7
    k_fused    <<<dim3(LQ/(2*KC), BH), 256>>>(Q, K, V, U);   // 8
    k_final    <<<dim3(NCH, BH), 64>>>(V, out);              // 9
}